// round 11
// baseline (speedup 1.0000x reference)
#include <cuda_runtime.h>
#include <cuda_bf16.h>

// Problem constants (fixed by the reference setup_inputs)
#define BB 64
#define SS 512
#define HH 768
#define WW 256      // MAX_WORD_LEN
#define WE 300
#define OUTW (HH + WE)   // 1068 floats
#define HV  (HH/4)       // 192 float4
#define WV  (WE/4)       // 75 float4
#define G   8            // words per CTA
#define NG  (WW/G)       // 32 groups per batch
#define NT  192          // threads: one float4 of H per thread

// One CTA per (batch, 8 consecutive words). token_ids sorted => the 8 words'
// tokens form ONE contiguous row range [l0, l8). Walk it linearly with a
// 4-deep register prefetch ring (static slots) so hidden loads stream at
// MLP~4 independent of word boundaries; boundaries come from broadcast LDS.
__global__ __launch_bounds__(NT)
void embeddings_stream_kernel(const float* __restrict__ hidden,
                              const float* __restrict__ w2v,
                              const int*   __restrict__ token_ids,
                              const int*   __restrict__ word_ids,
                              float*       __restrict__ out)
{
    const int gi  = blockIdx.x;          // 0 .. 2047
    const int b   = gi >> 5;             // / NG
    const int w0  = (gi & (NG - 1)) << 3;
    const int tid = threadIdx.x;         // 0 .. 191

    __shared__ int st[SS];

    // ---- start the 8 independent w2v gathers immediately (overlap DRAM/L2
    //      latency with everything below). Broadcast int4 word-id loads. ----
    const int4 wa = __ldg(reinterpret_cast<const int4*>(word_ids + b * WW + w0));
    const int4 wb = __ldg(reinterpret_cast<const int4*>(word_ids + b * WW + w0 + 4));
    const bool hasw = (tid < WV);
    float4 gv0, gv1, gv2, gv3, gv4, gv5, gv6, gv7;
    if (hasw) {
        gv0 = __ldg(reinterpret_cast<const float4*>(w2v + (size_t)wa.x * WE) + tid);
        gv1 = __ldg(reinterpret_cast<const float4*>(w2v + (size_t)wa.y * WE) + tid);
        gv2 = __ldg(reinterpret_cast<const float4*>(w2v + (size_t)wa.z * WE) + tid);
        gv3 = __ldg(reinterpret_cast<const float4*>(w2v + (size_t)wa.w * WE) + tid);
        gv4 = __ldg(reinterpret_cast<const float4*>(w2v + (size_t)wb.x * WE) + tid);
        gv5 = __ldg(reinterpret_cast<const float4*>(w2v + (size_t)wb.y * WE) + tid);
        gv6 = __ldg(reinterpret_cast<const float4*>(w2v + (size_t)wb.z * WE) + tid);
        gv7 = __ldg(reinterpret_cast<const float4*>(w2v + (size_t)wb.w * WE) + tid);
    }

    // ---- stage token_ids (128 threads x int4 = 512 ints, coalesced) ----
    if (tid < 128) {
        reinterpret_cast<int4*>(st)[tid] =
            __ldg(reinterpret_cast<const int4*>(token_ids + b * SS) + tid);
    }
    __syncthreads();

    // ---- two binary searches (broadcast LDS): l0=lb(w0), l8=lb(w0+8) ----
    int l0 = 0;
    { int hi = SS; while (l0 < hi) { int m = (l0 + hi) >> 1; if (st[m] < w0)     l0 = m + 1; else hi = m; } }
    int l8 = l0;
    { int hi = SS; while (l8 < hi) { int m = (l8 + hi) >> 1; if (st[m] < w0 + G) l8 = m + 1; else hi = m; } }

    const float4* hb = reinterpret_cast<const float4*>(hidden + (size_t)b * SS * HH);

    // ---- prime the 4-deep prefetch ring (static register slots) ----
    float4 p0, p1, p2, p3;
    const float4 z = make_float4(0.f, 0.f, 0.f, 0.f);
    p0 = (l0 + 0 < l8) ? __ldcs(&hb[(size_t)(l0 + 0) * HV + tid]) : z;
    p1 = (l0 + 1 < l8) ? __ldcs(&hb[(size_t)(l0 + 1) * HV + tid]) : z;
    p2 = (l0 + 2 < l8) ? __ldcs(&hb[(size_t)(l0 + 2) * HV + tid]) : z;
    p3 = (l0 + 3 < l8) ? __ldcs(&hb[(size_t)(l0 + 3) * HV + tid]) : z;

    int   cur = w0;
    int   cnt = 0;
    float4 acc = z;

    for (int sb = l0; sb < l8; sb += 4) {
        #pragma unroll
        for (int u = 0; u < 4; ++u) {
            const int s = sb + u;
            if (s < l8) {
                const int tw = st[s];                       // broadcast LDS
                if (tw != cur) {
                    const float inv = cnt ? (1.0f / (float)cnt) : 0.0f;
                    float4* orow = reinterpret_cast<float4*>(out + (size_t)(b * WW + cur) * OUTW);
                    float4 rr; rr.x = acc.x * inv; rr.y = acc.y * inv;
                    rr.z = acc.z * inv; rr.w = acc.w * inv;
                    __stcs(&orow[tid], rr);
                    for (int w = cur + 1; w < tw; ++w) {    // empty words -> zeros
                        float4* oz = reinterpret_cast<float4*>(out + (size_t)(b * WW + w) * OUTW);
                        __stcs(&oz[tid], z);
                    }
                    cur = tw; acc = z; cnt = 0;
                }
                float4 v;
                if (u == 0) { v = p0; if (s + 4 < l8) p0 = __ldcs(&hb[(size_t)(s + 4) * HV + tid]); }
                if (u == 1) { v = p1; if (s + 4 < l8) p1 = __ldcs(&hb[(size_t)(s + 4) * HV + tid]); }
                if (u == 2) { v = p2; if (s + 4 < l8) p2 = __ldcs(&hb[(size_t)(s + 4) * HV + tid]); }
                if (u == 3) { v = p3; if (s + 4 < l8) p3 = __ldcs(&hb[(size_t)(s + 4) * HV + tid]); }
                acc.x += v.x; acc.y += v.y; acc.z += v.z; acc.w += v.w;
                ++cnt;
            }
        }
    }

    // ---- tail: finalize current word, zero the rest of the group ----
    {
        const float inv = cnt ? (1.0f / (float)cnt) : 0.0f;
        float4* orow = reinterpret_cast<float4*>(out + (size_t)(b * WW + cur) * OUTW);
        float4 rr; rr.x = acc.x * inv; rr.y = acc.y * inv;
        rr.z = acc.z * inv; rr.w = acc.w * inv;
        __stcs(&orow[tid], rr);
        for (int w = cur + 1; w < w0 + G; ++w) {
            float4* oz = reinterpret_cast<float4*>(out + (size_t)(b * WW + w) * OUTW);
            __stcs(&oz[tid], z);
        }
    }

    // ---- gather epilogue: static unrolled, one float4 per thread per word ----
    if (hasw) {
        float* ob = out + (size_t)(b * WW + w0) * OUTW + HH;
        __stcs(reinterpret_cast<float4*>(ob + 0 * OUTW) + tid, gv0);
        __stcs(reinterpret_cast<float4*>(ob + 1 * OUTW) + tid, gv1);
        __stcs(reinterpret_cast<float4*>(ob + 2 * OUTW) + tid, gv2);
        __stcs(reinterpret_cast<float4*>(ob + 3 * OUTW) + tid, gv3);
        __stcs(reinterpret_cast<float4*>(ob + 4 * OUTW) + tid, gv4);
        __stcs(reinterpret_cast<float4*>(ob + 5 * OUTW) + tid, gv5);
        __stcs(reinterpret_cast<float4*>(ob + 6 * OUTW) + tid, gv6);
        __stcs(reinterpret_cast<float4*>(ob + 7 * OUTW) + tid, gv7);
    }
}

extern "C" void kernel_launch(void* const* d_in, const int* in_sizes, int n_in,
                              void* d_out, int out_size)
{
    // Identify inputs by element count (robust to ordering):
    //   hidden    : 64*512*768  = 25,165,824 (float32)
    //   w2v_table : 50000*300   = 15,000,000 (float32)
    //   token_ids : 64*512      = 32,768     (int32)
    //   word_ids  : 64*256      = 16,384     (int32)
    const float* hidden = nullptr;
    const float* w2v    = nullptr;
    const int*   tok    = nullptr;
    const int*   wids   = nullptr;
    for (int i = 0; i < n_in; ++i) {
        switch (in_sizes[i]) {
            case 25165824: hidden = (const float*)d_in[i]; break;
            case 15000000: w2v    = (const float*)d_in[i]; break;
            case 32768:    tok    = (const int*)d_in[i];   break;
            case 16384:    wids   = (const int*)d_in[i];   break;
            default: break;
        }
    }
    float* out = (float*)d_out;

    embeddings_stream_kernel<<<BB * NG, NT>>>(hidden, w2v, tok, wids, out);
}

// round 12
// speedup vs baseline: 1.4220x; 1.4220x over previous
#include <cuda_runtime.h>
#include <cuda_bf16.h>

// Problem constants (fixed by the reference setup_inputs)
#define BB 64
#define SS 512
#define HH 768
#define WW 256      // MAX_WORD_LEN
#define WE 300
#define OUTW (HH + WE)   // 1068 floats
#define HV  (HH/4)       // 192 float4
#define WV  (WE/4)       // 75 float4

// One CTA per (batch, word), 128 threads, 16384 CTAs (max parallelism — the
// shape that measured best). Bounds via parallel counting instead of binary
// search: token_ids sorted => lo = #ids < w, cnt = #ids == w. One coalesced
// int4 LDG per thread covers all 512 ids; redux.sync.add per warp + 4 smem
// partials + one barrier. No serial LDS search chain, no 2KB staging.
__global__ __launch_bounds__(128)
void embeddings_fused_kernel(const float* __restrict__ hidden,
                             const float* __restrict__ w2v,
                             const int*   __restrict__ token_ids,
                             const int*   __restrict__ word_ids,
                             float*       __restrict__ out)
{
    const int bw  = blockIdx.x;        // 0 .. B*W-1
    const int b   = bw >> 8;
    const int w   = bw & (WW - 1);
    const int tid = threadIdx.x;

    __shared__ int s_part[4];

    // ---- start the independent w2v gather early (overlaps everything) ----
    const int wid = __ldg(&word_ids[bw]);
    const bool hasw = (tid < WV);
    float4 gv;
    if (hasw) {
        gv = __ldg(reinterpret_cast<const float4*>(w2v + (size_t)wid * WE) + tid);
    }

    // ---- parallel bounds: one int4 chunk per thread (coalesced, L2-hot) ----
    const int4 tv = __ldg(reinterpret_cast<const int4*>(token_ids + b * SS) + tid);
    int c = (tv.x < w) + (tv.y < w) + (tv.z < w) + (tv.w < w);      // -> lo
    int d = (tv.x == w) + (tv.y == w) + (tv.z == w) + (tv.w == w);  // -> cnt
    int p = c | (d << 16);
    p = __reduce_add_sync(0xffffffffu, p);          // per-warp sum
    if ((tid & 31) == 0) s_part[tid >> 5] = p;
    __syncthreads();
    const int sum = s_part[0] + s_part[1] + s_part[2] + s_part[3];  // broadcast LDS
    const int lo  = sum & 0xffff;
    const int cnt = sum >> 16;
    const float inv = (cnt > 0) ? (1.0f / (float)cnt) : 0.0f;

    float4* orow = reinterpret_cast<float4*>(out + (size_t)bw * OUTW);

    // ---- transformer mean: 192 float4 over 128 threads (dual chains) ----
    const float4* r = reinterpret_cast<const float4*>(hidden + (size_t)b * SS * HH)
                      + (size_t)lo * HV;
    const bool has2 = (tid < (HV - 128));   // tid < 64
    float4 a0 = make_float4(0.f, 0.f, 0.f, 0.f);
    float4 a1 = make_float4(0.f, 0.f, 0.f, 0.f);
    #pragma unroll 1
    for (int s = 0; s < cnt; ++s, r += HV) {
        float4 v0 = __ldcs(&r[tid]);
        a0.x += v0.x; a0.y += v0.y; a0.z += v0.z; a0.w += v0.w;
        if (has2) {
            float4 v1 = __ldcs(&r[tid + 128]);
            a1.x += v1.x; a1.y += v1.y; a1.z += v1.z; a1.w += v1.w;
        }
    }
    a0.x *= inv; a0.y *= inv; a0.z *= inv; a0.w *= inv;
    __stcs(&orow[tid], a0);
    if (has2) {
        a1.x *= inv; a1.y *= inv; a1.z *= inv; a1.w *= inv;
        __stcs(&orow[tid + 128], a1);
    }
    if (hasw) {
        __stcs(&orow[HV + tid], gv);
    }
}

extern "C" void kernel_launch(void* const* d_in, const int* in_sizes, int n_in,
                              void* d_out, int out_size)
{
    // Identify inputs by element count (robust to ordering):
    //   hidden    : 64*512*768  = 25,165,824 (float32)
    //   w2v_table : 50000*300   = 15,000,000 (float32)
    //   token_ids : 64*512      = 32,768     (int32)
    //   word_ids  : 64*256      = 16,384     (int32)
    const float* hidden = nullptr;
    const float* w2v    = nullptr;
    const int*   tok    = nullptr;
    const int*   wids   = nullptr;
    for (int i = 0; i < n_in; ++i) {
        switch (in_sizes[i]) {
            case 25165824: hidden = (const float*)d_in[i]; break;
            case 15000000: w2v    = (const float*)d_in[i]; break;
            case 32768:    tok    = (const int*)d_in[i];   break;
            case 16384:    wids   = (const int*)d_in[i];   break;
            default: break;
        }
    }
    float* out = (float*)d_out;

    embeddings_fused_kernel<<<BB * WW, 128>>>(hidden, w2v, tok, wids, out);
}

// round 13
// speedup vs baseline: 1.8339x; 1.2897x over previous
#include <cuda_runtime.h>
#include <cuda_bf16.h>

// Problem constants (fixed by the reference setup_inputs)
#define BB 64
#define SS 512
#define HH 768
#define WW 256      // MAX_WORD_LEN
#define WE 300
#define OUTW (HH + WE)   // 1068 floats
#define HV  (HH/4)       // 192 float4
#define WV  (WE/4)       // 75 float4

// One CTA per (batch, word), 128 threads, 16384 CTAs. Bounds via parallel
// counting (sorted ids => lo = #ids<w, cnt = #ids==w). Reduction issues a
// 4-deep predicated prefetch for BOTH float4 chains before any FADD, so the
// common case (cnt<=4) runs at per-warp MLP~8 instead of 2; rare cnt>4 rows
// are handled by a serial remainder loop. Streaming hints on the one-shot
// hidden reads and output writes keep L2 for the w2v table and token_ids.
__global__ __launch_bounds__(128)
void embeddings_fused_kernel(const float* __restrict__ hidden,
                             const float* __restrict__ w2v,
                             const int*   __restrict__ token_ids,
                             const int*   __restrict__ word_ids,
                             float*       __restrict__ out)
{
    const int bw  = blockIdx.x;        // 0 .. B*W-1
    const int b   = bw >> 8;
    const int w   = bw & (WW - 1);
    const int tid = threadIdx.x;

    __shared__ int s_part[4];

    // ---- start the independent w2v gather early (overlaps everything) ----
    const int wid = __ldg(&word_ids[bw]);
    const bool hasw = (tid < WV);
    float4 gv;
    if (hasw) {
        gv = __ldg(reinterpret_cast<const float4*>(w2v + (size_t)wid * WE) + tid);
    }

    // ---- parallel bounds: one int4 chunk per thread (coalesced, L2-hot) ----
    const int4 tv = __ldg(reinterpret_cast<const int4*>(token_ids + b * SS) + tid);
    int c = (tv.x < w) + (tv.y < w) + (tv.z < w) + (tv.w < w);      // -> lo
    int d = (tv.x == w) + (tv.y == w) + (tv.z == w) + (tv.w == w);  // -> cnt
    int p = c | (d << 16);
    p = __reduce_add_sync(0xffffffffu, p);          // per-warp sum
    if ((tid & 31) == 0) s_part[tid >> 5] = p;
    __syncthreads();
    const int sum = s_part[0] + s_part[1] + s_part[2] + s_part[3];  // broadcast LDS
    const int lo  = sum & 0xffff;
    const int cnt = sum >> 16;
    const float inv = (cnt > 0) ? (1.0f / (float)cnt) : 0.0f;

    float4* orow = reinterpret_cast<float4*>(out + (size_t)bw * OUTW);

    const float4* rbase = reinterpret_cast<const float4*>(hidden + (size_t)b * SS * HH)
                          + (size_t)lo * HV;
    const bool has2 = (tid < (HV - 128));   // tid < 64
    const float4 z = make_float4(0.f, 0.f, 0.f, 0.f);

    // ---- 4-deep predicated prefetch, both chains, before any FADD ----
    const float4* c0 = rbase + tid;
    const float4* c1 = rbase + tid + 128;
    float4 t0 = (cnt > 0) ? __ldcs(c0 + 0 * HV) : z;
    float4 t1 = (cnt > 1) ? __ldcs(c0 + 1 * HV) : z;
    float4 t2 = (cnt > 2) ? __ldcs(c0 + 2 * HV) : z;
    float4 t3 = (cnt > 3) ? __ldcs(c0 + 3 * HV) : z;
    float4 u0 = (has2 && cnt > 0) ? __ldcs(c1 + 0 * HV) : z;
    float4 u1 = (has2 && cnt > 1) ? __ldcs(c1 + 1 * HV) : z;
    float4 u2 = (has2 && cnt > 2) ? __ldcs(c1 + 2 * HV) : z;
    float4 u3 = (has2 && cnt > 3) ? __ldcs(c1 + 3 * HV) : z;

    // tree-sum the prefetched rows
    float4 a0, a1;
    a0.x = (t0.x + t1.x) + (t2.x + t3.x);
    a0.y = (t0.y + t1.y) + (t2.y + t3.y);
    a0.z = (t0.z + t1.z) + (t2.z + t3.z);
    a0.w = (t0.w + t1.w) + (t2.w + t3.w);
    a1.x = (u0.x + u1.x) + (u2.x + u3.x);
    a1.y = (u0.y + u1.y) + (u2.y + u3.y);
    a1.z = (u0.z + u1.z) + (u2.z + u3.z);
    a1.w = (u0.w + u1.w) + (u2.w + u3.w);

    // ---- rare remainder (cnt > 4) ----
    #pragma unroll 1
    for (int s = 4; s < cnt; ++s) {
        float4 v0 = __ldcs(c0 + (size_t)s * HV);
        a0.x += v0.x; a0.y += v0.y; a0.z += v0.z; a0.w += v0.w;
        if (has2) {
            float4 v1 = __ldcs(c1 + (size_t)s * HV);
            a1.x += v1.x; a1.y += v1.y; a1.z += v1.z; a1.w += v1.w;
        }
    }

    a0.x *= inv; a0.y *= inv; a0.z *= inv; a0.w *= inv;
    __stcs(&orow[tid], a0);
    if (has2) {
        a1.x *= inv; a1.y *= inv; a1.z *= inv; a1.w *= inv;
        __stcs(&orow[tid + 128], a1);
    }
    if (hasw) {
        __stcs(&orow[HV + tid], gv);
    }
}

extern "C" void kernel_launch(void* const* d_in, const int* in_sizes, int n_in,
                              void* d_out, int out_size)
{
    // Identify inputs by element count (robust to ordering):
    //   hidden    : 64*512*768  = 25,165,824 (float32)
    //   w2v_table : 50000*300   = 15,000,000 (float32)
    //   token_ids : 64*512      = 32,768     (int32)
    //   word_ids  : 64*256      = 16,384     (int32)
    const float* hidden = nullptr;
    const float* w2v    = nullptr;
    const int*   tok    = nullptr;
    const int*   wids   = nullptr;
    for (int i = 0; i < n_in; ++i) {
        switch (in_sizes[i]) {
            case 25165824: hidden = (const float*)d_in[i]; break;
            case 15000000: w2v    = (const float*)d_in[i]; break;
            case 32768:    tok    = (const int*)d_in[i];   break;
            case 16384:    wids   = (const int*)d_in[i];   break;
            default: break;
        }
    }
    float* out = (float*)d_out;

    embeddings_fused_kernel<<<BB * WW, 128>>>(hidden, w2v, tok, wids, out);
}